// round 12
// baseline (speedup 1.0000x reference)
#include <cuda_runtime.h>
#include <cuda_bf16.h>
#include <cstdint>

typedef unsigned long long ull;

#define M_MODELS 3
#define B_IMG    16
#define N_BOX    512
#define K_TOT    (M_MODELS * N_BOX)   // 1536
#define PAD      2048
#define NUM_CLS  12
#define CAPB     192                  // per-bucket fast-path capacity
#define WB       3                    // CAPB/64 mask words per row
#define SORT_THR 512
#define NMS_THR  512
#define NMS_GRID (B_IMG * (NUM_CLS / 2))   // 96 blocks, 2 buckets each

// ---------------- device scratch (bucket-ordered, written by k_sort) ----------
__device__ float4 g_bbx [B_IMG * K_TOT];   // boxes, bucket order
__device__ float4 g_aux [B_IMG * K_TOT];   // (score, area, rank, 0), bucket order
__device__ int    g_boff[B_IMG * NUM_CLS];
__device__ int    g_bcnt[B_IMG * NUM_CLS];

__device__ __forceinline__ void cswap(ull& x, ull& y, bool up) {
    if ((x > y) == up) { ull t = x; x = y; y = t; }
}

__device__ __forceinline__ ull shfl_stage(ull v, int e, unsigned j, unsigned ks) {
    const ull  o     = __shfl_xor_sync(0xffffffffu, v, j);
    const bool up    = ((e & ks) == 0);
    const bool lower = ((e & j) == 0);
    return ((v < o) == (lower == up)) ? v : o;
}

// division-free exact IoU>0.5 test: 0.5*d is exact in fp32
__device__ __forceinline__ bool iou_gt(const float4 bi, const float ai,
                                       const float4 bj, const float aj) {
    const float iw = fmaxf(fminf(bi.z, bj.z) - fmaxf(bi.x, bj.x), 0.0f);
    const float ih = fmaxf(fminf(bi.w, bj.w) - fmaxf(bi.y, bj.y), 0.0f);
    const float inter = iw * ih;
    const float uni   = ai + aj - inter;
    return inter > 0.5f * fmaxf(uni, 1e-9f);
}

__device__ __forceinline__ void pdl_launch_dependents() {
    asm volatile("griddepcontrol.launch_dependents;");
}
__device__ __forceinline__ void pdl_wait() {
    asm volatile("griddepcontrol.wait;" ::: "memory");
}

// =============================================================================
// K1: sort (score desc, idx asc) + class compaction + bucket-ordered scatter.
// 512 threads, 4 elements/thread; warp owns a contiguous 128-element window
// (lane l holds e = W0 + l + 32k, k=0..3). Stages j<=64 are warp-local:
// j=64 and j=32 are in-thread cswaps, j<=16 via shfl. Only j>=128 stages go
// through smem: 10 stages + 4 reload barriers (was 15 stages / 20 barriers).
// =============================================================================
__global__ __launch_bounds__(SORT_THR)
void k_sort(const float* __restrict__ boxes, const float* __restrict__ scores,
            const int* __restrict__ labels, const float* __restrict__ weights) {
    extern __shared__ char dyn[];
    ull*    key  = (ull*)dyn;                    // 16384 B
    float4* sbox = (float4*)(dyn + PAD * 8);     // 24576 B (sorted boxes)
    __shared__ short slab[K_TOT];
    __shared__ short sidx[K_TOT];                // bucket pos -> rank
    __shared__ int   soff[NUM_CLS], scnt[NUM_CLS];

    pdl_launch_dependents();   // stage k_nms blocks early; they wait on data

    const int b    = blockIdx.x;
    const int tid  = threadIdx.x;
    const int warp = tid >> 5, lane = tid & 31;
    const int W0   = warp << 7;                  // 128-element window base

    const float w0 = weights[0], w1 = weights[1], w2 = weights[2];

    auto mkkey = [&](int s) -> ull {
        if (s >= K_TOT) return ~0ull;
        const int m = s >> 9, n = s & (N_BOX - 1);
        const float wm = (m == 0) ? w0 : ((m == 1) ? w1 : w2);
        const float sc = scores[(m * B_IMG + b) * N_BOX + n] * wm;
        return ((ull)(~__float_as_uint(sc)) << 32) | (unsigned)s;
    };

    int e0 = W0 + lane, e1 = e0 + 32, e2 = e0 + 64, e3 = e0 + 96;
    ull v0 = mkkey(e0), v1 = mkkey(e1), v2 = mkkey(e2), v3 = mkkey(e3);

    // ---- register phase: kstage 2..128 fully warp-local ----
    #pragma unroll
    for (int kb = 1; kb <= 5; kb++) {            // ks = 2,4,8,16,32
        const unsigned ks = 1u << kb;
        const unsigned jstart = (ks > 32) ? 16u : (ks >> 1);
        #pragma unroll
        for (unsigned j = jstart; j >= 1; j >>= 1) {
            v0 = shfl_stage(v0, e0, j, ks);
            v1 = shfl_stage(v1, e1, j, ks);
            v2 = shfl_stage(v2, e2, j, ks);
            v3 = shfl_stage(v3, e3, j, ks);
        }
    }
    {   // ks = 64: j=32 in-thread, then j=16..1 shfl
        const unsigned ks = 64;
        cswap(v0, v1, ((e0 & ks) == 0));
        cswap(v2, v3, ((e2 & ks) == 0));
        #pragma unroll
        for (unsigned j = 16; j >= 1; j >>= 1) {
            v0 = shfl_stage(v0, e0, j, ks);
            v1 = shfl_stage(v1, e1, j, ks);
            v2 = shfl_stage(v2, e2, j, ks);
            v3 = shfl_stage(v3, e3, j, ks);
        }
    }
    {   // ks = 128: j=64, j=32 in-thread (dir uniform in warp), then shfl
        const unsigned ks = 128;
        const bool up = ((e0 & ks) == 0);
        cswap(v0, v2, up); cswap(v1, v3, up);    // j = 64
        cswap(v0, v1, up); cswap(v2, v3, up);    // j = 32
        #pragma unroll
        for (unsigned j = 16; j >= 1; j >>= 1) {
            v0 = shfl_stage(v0, e0, j, ks);
            v1 = shfl_stage(v1, e1, j, ks);
            v2 = shfl_stage(v2, e2, j, ks);
            v3 = shfl_stage(v3, e3, j, ks);
        }
    }
    key[e0] = v0; key[e1] = v1; key[e2] = v2; key[e3] = v3;

    // ---- smem phase: kstage 256..2048, only j>=128 through smem ----
    #pragma unroll
    for (unsigned ks = 256; ks <= PAD; ks <<= 1) {
        for (unsigned j = ks >> 1; j >= 128; j >>= 1) {
            __syncthreads();
            #pragma unroll
            for (int t = tid; t < 1024; t += SORT_THR) {
                const unsigned i = (((unsigned)t & ~(j - 1)) << 1) | ((unsigned)t & (j - 1));
                const unsigned p = i | j;
                const ull x = key[i];
                const ull y = key[p];
                const bool up = ((i & ks) == 0);
                if ((x > y) == up) { key[i] = y; key[p] = x; }
            }
        }
        __syncthreads();
        v0 = key[e0]; v1 = key[e1]; v2 = key[e2]; v3 = key[e3];
        const bool up = ((e0 & ks) == 0);        // uniform per warp (ks>=256)
        cswap(v0, v2, up); cswap(v1, v3, up);    // j = 64
        cswap(v0, v1, up); cswap(v2, v3, up);    // j = 32
        #pragma unroll
        for (unsigned j = 16; j >= 1; j >>= 1) {
            v0 = shfl_stage(v0, e0, j, ks);
            v1 = shfl_stage(v1, e1, j, ks);
            v2 = shfl_stage(v2, e2, j, ks);
            v3 = shfl_stage(v3, e3, j, ks);
        }
        key[e0] = v0; key[e1] = v1; key[e2] = v2; key[e3] = v3;
    }
    __syncthreads();

    // ---- gather sorted boxes + labels into smem ----
    for (int r = tid; r < K_TOT; r += SORT_THR) {
        const int e = (int)(key[r] & 0xffffffffu);
        const int m = e >> 9, n = e & (N_BOX - 1);
        const size_t src = ((size_t)m * B_IMG + b) * N_BOX + n;
        sbox[r] = *(const float4*)&boxes[src * 4];
        slab[r] = (short)labels[src];
    }
    __syncthreads();

    // ---- stable per-class compaction (warp l = class l; 12 of 16 warps) ----
    if (warp < NUM_CLS) {
        int cnt = 0;
        for (int base = 0; base < K_TOT; base += 32) {
            const bool m = (slab[base + lane] == (short)warp);
            cnt += __popc(__ballot_sync(0xffffffffu, m));
        }
        if (lane == 0) scnt[warp] = cnt;
    }
    __syncthreads();
    if (tid == 0) {
        int acc = 0;
        #pragma unroll
        for (int l = 0; l < NUM_CLS; l++) { soff[l] = acc; acc += scnt[l]; }
    }
    __syncthreads();
    if (warp < NUM_CLS) {
        const int off = soff[warp];
        int cnt = 0;
        for (int base = 0; base < K_TOT; base += 32) {
            const bool m = (slab[base + lane] == (short)warp);
            const unsigned bal = __ballot_sync(0xffffffffu, m);
            if (m) {
                const int pos = cnt + __popc(bal & ((1u << lane) - 1u));
                sidx[off + pos] = (short)(base + lane);
            }
            cnt += __popc(bal);
        }
        if (lane == 0) {
            g_boff[b * NUM_CLS + warp] = off;
            g_bcnt[b * NUM_CLS + warp] = cnt;
        }
    }
    __syncthreads();

    // ---- bucket-ordered scatter to global ----
    for (int e = tid; e < K_TOT; e += SORT_THR) {
        const int rank = sidx[e];
        const size_t dst = (size_t)b * K_TOT + e;
        const float4 bb = sbox[rank];
        g_bbx[dst] = bb;
        g_aux[dst] = make_float4(__uint_as_float(~(unsigned)(key[rank] >> 32)),
                                 (bb.z - bb.x) * (bb.w - bb.y),
                                 (float)rank, 0.0f);
    }
}

// =============================================================================
// K2: NMS, TWO buckets per block (grid 96 < #SMs -> single wave).
// side = tid>>8 owns one bucket for load/output; warps 0-7 build bucket 0,
// warps 8-15 build bucket 1; the two serial chases run in parallel
// (tid 0 / tid 256). Output data kept in per-thread registers.
// =============================================================================
__global__ __launch_bounds__(NMS_THR)
void k_nms(float* __restrict__ out) {
    __shared__ float4 bx[2][CAPB];
    __shared__ float  ar[2][CAPB];
    __shared__ ull    smask[2][CAPB * WB];     // 9 KB
    __shared__ ull    rownz[2][WB];
    __shared__ ull    keepw[2][WB];
    __shared__ short  kidx[2][K_TOT];          // fallback kept lists

    const int img  = blockIdx.x / (NUM_CLS / 2);
    const int cp   = blockIdx.x % (NUM_CLS / 2);
    const int tid  = threadIdx.x;
    const int warp = tid >> 5, lane = tid & 31;
    const int side = tid >> 8;                 // load/output bucket
    const int m    = tid & 255;

    if (tid < 2 * WB) { rownz[tid / WB][tid % WB] = 0ull;
                        keepw[tid / WB][tid % WB] = ~0ull; }

    pdl_wait();   // k_sort's writes visible from here

    const int offA = g_boff[img * NUM_CLS + cp * 2];
    const int cntA = g_bcnt[img * NUM_CLS + cp * 2];
    const int offB = g_boff[img * NUM_CLS + cp * 2 + 1];
    const int cntB = g_bcnt[img * NUM_CLS + cp * 2 + 1];
    const bool fastA = (cntA <= CAPB), fastB = (cntB <= CAPB);

    const int   myOff  = side ? offB : offA;
    const int   myCnt  = side ? cntB : cntA;
    const bool  myFast = side ? fastB : fastA;
    const size_t gbase = (size_t)img * K_TOT + myOff;

    // ---- load: one element per thread, kept in registers ----
    float4 bb, ax;
    const bool own = myFast && (m < myCnt);
    if (own) {
        bb = g_bbx[gbase + m];
        ax = g_aux[gbase + m];
        bx[side][m] = bb;
        ar[side][m] = ax.y;
    }
    __syncthreads();

    // ---- build: warps 0-7 bucket A, 8-15 bucket B ----
    {
        const int bkt = warp >> 3;
        const int wi  = warp & 7;
        const int cnt = bkt ? cntB : cntA;
        if ((bkt ? fastB : fastA)) {
            const int W = (cnt + 63) >> 6;
            for (int r = wi; r < cnt; r += 8) {
                const float4 bi = bx[bkt][r];
                const float  ai = ar[bkt][r];
                ull nz = 0ull;
                for (int w = r >> 6; w < W; w++) {
                    const int j0 = w * 64 + lane;
                    const int j1 = j0 + 32;
                    bool p0 = false, p1 = false;
                    if (j0 > r && j0 < cnt) p0 = iou_gt(bi, ai, bx[bkt][j0], ar[bkt][j0]);
                    if (j1 > r && j1 < cnt) p1 = iou_gt(bi, ai, bx[bkt][j1], ar[bkt][j1]);
                    const unsigned lo = __ballot_sync(0xffffffffu, p0);
                    const unsigned hi = __ballot_sync(0xffffffffu, p1);
                    const ull mword = ((ull)hi << 32) | lo;
                    if (lane == 0) smask[bkt][r * WB + w] = mword;
                    nz |= mword;
                }
                if (lane == 0 && nz)
                    atomicOr(&rownz[bkt][r >> 6], 1ull << (r & 63));
            }
        }
    }
    __syncthreads();

    // ---- chase: two serial chases in parallel (tid 0 and tid 256) ----
    if (m == 0) {
        const int bkt = side;
        const int cnt = myCnt;
        if (myFast && cnt > 0) {
            const int W = (cnt + 63) >> 6;
            ull rem0 = 0, rem1 = 0, rem2 = 0;
            #pragma unroll
            for (int w = 0; w < WB; w++) {
                if (w >= W) break;
                ull act = rownz[bkt][w];
                ull rw  = (w == 0) ? rem0 : (w == 1) ? rem1 : rem2;
                act &= ~rw;
                while (act) {
                    const int bit = __ffsll((long long)act) - 1;
                    act &= act - 1;
                    if (!((rw >> bit) & 1ull)) {
                        const int i = w * 64 + bit;
                        const ull* row = &smask[bkt][i * WB];
                        if (w <= 0)          rem0 |= row[0];
                        if (w <= 1 && W > 1) rem1 |= row[1];
                        if (w <= 2 && W > 2) rem2 |= row[2];
                        rw = (w == 0) ? rem0 : (w == 1) ? rem1 : rem2;
                        act &= ~rw;
                    }
                }
            }
            keepw[bkt][0] = ~rem0; keepw[bkt][1] = ~rem1; keepw[bkt][2] = ~rem2;
        }
    }

    // ---- fallback (cnt > CAPB, pathological only): warp 4 = A, warp 12 = B ----
    if ((warp == 4 && !fastA) || (warp == 12 && !fastB)) {
        const int   bkt  = warp >> 3;
        const int   cnt  = bkt ? cntB : cntA;
        const size_t gb  = (size_t)img * K_TOT + (bkt ? offB : offA);
        int nk = 0;
        for (int cix = 0; cix < cnt; cix++) {
            const float4 bc = g_bbx[gb + cix];
            const float  ac = (bc.z - bc.x) * (bc.w - bc.y);
            bool sup = false;
            for (int k = lane; k < nk; k += 32) {
                const float4 bk = g_bbx[gb + kidx[bkt][k]];
                const float  ak = (bk.z - bk.x) * (bk.w - bk.y);
                if (iou_gt(bc, ac, bk, ak)) { sup = true; break; }
            }
            sup = (__ballot_sync(0xffffffffu, sup) != 0u);
            if (!sup) {
                if (lane == 0) kidx[bkt][nk] = (short)cix;
                nk++;
            }
            if (lane == 0) {
                const float4 axf = g_aux[gb + cix];
                const float f = sup ? 0.0f : 1.0f;
                const size_t o = ((size_t)img * K_TOT + (int)axf.z) * 5;
                out[o + 0] = bc.x * f;
                out[o + 1] = bc.y * f;
                out[o + 2] = bc.z * f;
                out[o + 3] = bc.w * f;
                out[o + 4] = axf.x * f;
            }
            __syncwarp();
        }
    }
    __syncthreads();

    // ---- output from registers ----
    if (own) {
        const bool kp = (keepw[side][m >> 6] >> (m & 63)) & 1ull;
        const float f = kp ? 1.0f : 0.0f;
        const size_t o = ((size_t)img * K_TOT + (int)ax.z) * 5;
        out[o + 0] = bb.x * f;
        out[o + 1] = bb.y * f;
        out[o + 2] = bb.z * f;
        out[o + 3] = bb.w * f;
        out[o + 4] = ax.x * f;
    }
}

// =============================================================================
extern "C" void kernel_launch(void* const* d_in, const int* in_sizes, int n_in,
                              void* d_out, int out_size) {
    const float* boxes   = (const float*)d_in[0];
    const float* scores  = (const float*)d_in[1];
    const int*   labels  = (const int*)  d_in[2];
    const float* weights = (const float*)d_in[3];
    float*       out     = (float*)d_out;

    k_sort<<<B_IMG, SORT_THR, PAD * 8 + K_TOT * 16>>>(boxes, scores, labels, weights);

    cudaLaunchConfig_t cfg = {};
    cfg.gridDim  = dim3(NMS_GRID);
    cfg.blockDim = dim3(NMS_THR);
    cfg.dynamicSmemBytes = 0;
    cfg.stream = 0;
    cudaLaunchAttribute attr[1];
    attr[0].id = cudaLaunchAttributeProgrammaticStreamSerialization;
    attr[0].val.programmaticStreamSerializationAllowed = 1;
    cfg.attrs = attr;
    cfg.numAttrs = 1;
    cudaLaunchKernelEx(&cfg, k_nms, out);
}

// round 13
// speedup vs baseline: 1.0438x; 1.0438x over previous
#include <cuda_runtime.h>
#include <cuda_bf16.h>
#include <cstdint>

typedef unsigned long long ull;

#define M_MODELS 3
#define B_IMG    16
#define N_BOX    512
#define K_TOT    (M_MODELS * N_BOX)   // 1536
#define PAD      2048
#define NUM_CLS  12
#define CAP      256                  // fast-path bucket capacity
#define W_MAX    4                    // CAP/64 mask words per row
#define SORT_THR 512
#define NMS_THR  512                  // 16 warps

// ---------------- device scratch (bucket-ordered, written by k_sort) ----------
__device__ float4 g_bbx [B_IMG * K_TOT];   // boxes, bucket order
__device__ float4 g_aux [B_IMG * K_TOT];   // (score, area, rank, 0), bucket order
__device__ int    g_boff[B_IMG * NUM_CLS];
__device__ int    g_bcnt[B_IMG * NUM_CLS];

__device__ __forceinline__ void cswap(ull& x, ull& y, bool up) {
    if ((x > y) == up) { ull t = x; x = y; y = t; }
}

__device__ __forceinline__ ull shfl_stage(ull v, int e, unsigned j, unsigned ks) {
    const ull  o     = __shfl_xor_sync(0xffffffffu, v, j);
    const bool up    = ((e & ks) == 0);
    const bool lower = ((e & j) == 0);
    return ((v < o) == (lower == up)) ? v : o;
}

// division-free exact IoU>0.5 test: 0.5*d is exact in fp32
__device__ __forceinline__ bool iou_gt(const float4 bi, const float ai,
                                       const float4 bj, const float aj) {
    const float iw = fmaxf(fminf(bi.z, bj.z) - fmaxf(bi.x, bj.x), 0.0f);
    const float ih = fmaxf(fminf(bi.w, bj.w) - fmaxf(bi.y, bj.y), 0.0f);
    const float inter = iw * ih;
    const float uni   = ai + aj - inter;
    return inter > 0.5f * fmaxf(uni, 1e-9f);
}

__device__ __forceinline__ void pdl_launch_dependents() {
    asm volatile("griddepcontrol.launch_dependents;");
}
__device__ __forceinline__ void pdl_wait() {
    asm volatile("griddepcontrol.wait;" ::: "memory");
}

// =============================================================================
// K1: sort (score desc, idx asc) + class compaction + bucket-ordered scatter.
// 512 threads, 4 elements/thread; warp owns a contiguous 128-element window.
// Stages j<=64 warp-local (j=64/32 in-thread, j<=16 shfl); j>=128 via smem.
// =============================================================================
__global__ __launch_bounds__(SORT_THR)
void k_sort(const float* __restrict__ boxes, const float* __restrict__ scores,
            const int* __restrict__ labels, const float* __restrict__ weights) {
    extern __shared__ char dyn[];
    ull*    key  = (ull*)dyn;                    // 16384 B
    float4* sbox = (float4*)(dyn + PAD * 8);     // 24576 B (sorted boxes)
    __shared__ short slab[K_TOT];
    __shared__ short sidx[K_TOT];                // bucket pos -> rank
    __shared__ int   soff[NUM_CLS], scnt[NUM_CLS];

    pdl_launch_dependents();   // stage k_nms blocks early; they wait on data

    const int b    = blockIdx.x;
    const int tid  = threadIdx.x;
    const int warp = tid >> 5, lane = tid & 31;
    const int W0   = warp << 7;                  // 128-element window base

    const float w0 = weights[0], w1 = weights[1], w2 = weights[2];

    auto mkkey = [&](int s) -> ull {
        if (s >= K_TOT) return ~0ull;
        const int m = s >> 9, n = s & (N_BOX - 1);
        const float wm = (m == 0) ? w0 : ((m == 1) ? w1 : w2);
        const float sc = scores[(m * B_IMG + b) * N_BOX + n] * wm;
        return ((ull)(~__float_as_uint(sc)) << 32) | (unsigned)s;
    };

    int e0 = W0 + lane, e1 = e0 + 32, e2 = e0 + 64, e3 = e0 + 96;
    ull v0 = mkkey(e0), v1 = mkkey(e1), v2 = mkkey(e2), v3 = mkkey(e3);

    // ---- register phase: kstage 2..128 fully warp-local ----
    #pragma unroll
    for (int kb = 1; kb <= 5; kb++) {            // ks = 2,4,8,16,32
        const unsigned ks = 1u << kb;
        const unsigned jstart = (ks > 32) ? 16u : (ks >> 1);
        #pragma unroll
        for (unsigned j = jstart; j >= 1; j >>= 1) {
            v0 = shfl_stage(v0, e0, j, ks);
            v1 = shfl_stage(v1, e1, j, ks);
            v2 = shfl_stage(v2, e2, j, ks);
            v3 = shfl_stage(v3, e3, j, ks);
        }
    }
    {   // ks = 64
        const unsigned ks = 64;
        cswap(v0, v1, ((e0 & ks) == 0));
        cswap(v2, v3, ((e2 & ks) == 0));
        #pragma unroll
        for (unsigned j = 16; j >= 1; j >>= 1) {
            v0 = shfl_stage(v0, e0, j, ks);
            v1 = shfl_stage(v1, e1, j, ks);
            v2 = shfl_stage(v2, e2, j, ks);
            v3 = shfl_stage(v3, e3, j, ks);
        }
    }
    {   // ks = 128
        const unsigned ks = 128;
        const bool up = ((e0 & ks) == 0);
        cswap(v0, v2, up); cswap(v1, v3, up);    // j = 64
        cswap(v0, v1, up); cswap(v2, v3, up);    // j = 32
        #pragma unroll
        for (unsigned j = 16; j >= 1; j >>= 1) {
            v0 = shfl_stage(v0, e0, j, ks);
            v1 = shfl_stage(v1, e1, j, ks);
            v2 = shfl_stage(v2, e2, j, ks);
            v3 = shfl_stage(v3, e3, j, ks);
        }
    }
    key[e0] = v0; key[e1] = v1; key[e2] = v2; key[e3] = v3;

    // ---- smem phase: kstage 256..2048, only j>=128 through smem ----
    #pragma unroll
    for (unsigned ks = 256; ks <= PAD; ks <<= 1) {
        for (unsigned j = ks >> 1; j >= 128; j >>= 1) {
            __syncthreads();
            #pragma unroll
            for (int t = tid; t < 1024; t += SORT_THR) {
                const unsigned i = (((unsigned)t & ~(j - 1)) << 1) | ((unsigned)t & (j - 1));
                const unsigned p = i | j;
                const ull x = key[i];
                const ull y = key[p];
                const bool up = ((i & ks) == 0);
                if ((x > y) == up) { key[i] = y; key[p] = x; }
            }
        }
        __syncthreads();
        v0 = key[e0]; v1 = key[e1]; v2 = key[e2]; v3 = key[e3];
        const bool up = ((e0 & ks) == 0);        // uniform per warp (ks>=256)
        cswap(v0, v2, up); cswap(v1, v3, up);    // j = 64
        cswap(v0, v1, up); cswap(v2, v3, up);    // j = 32
        #pragma unroll
        for (unsigned j = 16; j >= 1; j >>= 1) {
            v0 = shfl_stage(v0, e0, j, ks);
            v1 = shfl_stage(v1, e1, j, ks);
            v2 = shfl_stage(v2, e2, j, ks);
            v3 = shfl_stage(v3, e3, j, ks);
        }
        key[e0] = v0; key[e1] = v1; key[e2] = v2; key[e3] = v3;
    }
    __syncthreads();

    // ---- gather sorted boxes + labels into smem ----
    for (int r = tid; r < K_TOT; r += SORT_THR) {
        const int e = (int)(key[r] & 0xffffffffu);
        const int m = e >> 9, n = e & (N_BOX - 1);
        const size_t src = ((size_t)m * B_IMG + b) * N_BOX + n;
        sbox[r] = *(const float4*)&boxes[src * 4];
        slab[r] = (short)labels[src];
    }
    __syncthreads();

    // ---- stable per-class compaction (warp l = class l) ----
    if (warp < NUM_CLS) {
        int cnt = 0;
        for (int base = 0; base < K_TOT; base += 32) {
            const bool m = (slab[base + lane] == (short)warp);
            cnt += __popc(__ballot_sync(0xffffffffu, m));
        }
        if (lane == 0) scnt[warp] = cnt;
    }
    __syncthreads();
    if (tid == 0) {
        int acc = 0;
        #pragma unroll
        for (int l = 0; l < NUM_CLS; l++) { soff[l] = acc; acc += scnt[l]; }
    }
    __syncthreads();
    if (warp < NUM_CLS) {
        const int off = soff[warp];
        int cnt = 0;
        for (int base = 0; base < K_TOT; base += 32) {
            const bool m = (slab[base + lane] == (short)warp);
            const unsigned bal = __ballot_sync(0xffffffffu, m);
            if (m) {
                const int pos = cnt + __popc(bal & ((1u << lane) - 1u));
                sidx[off + pos] = (short)(base + lane);
            }
            cnt += __popc(bal);
        }
        if (lane == 0) {
            g_boff[b * NUM_CLS + warp] = off;
            g_bcnt[b * NUM_CLS + warp] = cnt;
        }
    }
    __syncthreads();

    // ---- bucket-ordered scatter to global ----
    for (int e = tid; e < K_TOT; e += SORT_THR) {
        const int rank = sidx[e];
        const size_t dst = (size_t)b * K_TOT + e;
        const float4 bb = sbox[rank];
        g_bbx[dst] = bb;
        g_aux[dst] = make_float4(__uint_as_float(~(unsigned)(key[rank] >> 32)),
                                 (bb.z - bb.x) * (bb.w - bb.y),
                                 (float)rank, 0.0f);
    }
}

// =============================================================================
// K2: per-(image,class) NMS, 512 threads, one bucket per block (192 blocks).
// Bucket padded in SMEM to a multiple of 64 with sentinel boxes (never
// suppress) -> inner loop has NO j<cnt / j>r branches; the diagonal word is
// cleaned with a post-ballot bitmask. Single-thread register-resident sparse
// greedy chase; output from SMEM.
// =============================================================================
__global__ __launch_bounds__(NMS_THR)
void k_nms(float* __restrict__ out) {
    __shared__ float4 bx[CAP];
    __shared__ float  ar[CAP];
    __shared__ float  sc[CAP];
    __shared__ short  rk[CAP];
    __shared__ ull    smask[CAP * W_MAX];     // 8 KB
    __shared__ ull    rownz[W_MAX];
    __shared__ ull    keepw[W_MAX];

    const int img  = blockIdx.x / NUM_CLS;
    const int cls  = blockIdx.x % NUM_CLS;
    const int tid  = threadIdx.x;
    const int warp = tid >> 5, lane = tid & 31;

    if (tid < W_MAX) { rownz[tid] = 0ull; keepw[tid] = ~0ull; }

    pdl_wait();   // k_sort's writes visible from here

    const int off = g_boff[img * NUM_CLS + cls];
    const int cnt = g_bcnt[img * NUM_CLS + cls];
    if (cnt == 0) return;

    const size_t gbase = (size_t)img * K_TOT + off;

    if (cnt <= CAP) {
        const int W    = (cnt + 63) >> 6;
        const int cpad = W << 6;
        // ---- load + sentinel padding ----
        for (int m = tid; m < cpad; m += NMS_THR) {
            if (m < cnt) {
                const float4 bb = g_bbx[gbase + m];
                const float4 ax = g_aux[gbase + m];
                bx[m] = bb;
                ar[m] = ax.y;
                sc[m] = ax.x;
                rk[m] = (short)ax.z;
            } else {
                bx[m] = make_float4(3e8f, 3e8f, 3e8f, 3e8f);  // never suppresses
                ar[m] = 0.0f;
            }
        }
        __syncthreads();

        // ---- branch-free matrix build: rows striped over 16 warps ----
        for (int r = warp; r < cnt; r += 16) {
            const float4 bi = bx[r];
            const float  ai = ar[r];
            const int    w0 = r >> 6;
            ull nz = 0ull;
            for (int w = w0; w < W; w++) {
                const int j0 = (w << 6) + lane;
                const bool p0 = iou_gt(bi, ai, bx[j0],      ar[j0]);
                const bool p1 = iou_gt(bi, ai, bx[j0 + 32], ar[j0 + 32]);
                ull mword = ((ull)__ballot_sync(0xffffffffu, p1) << 32)
                          |        __ballot_sync(0xffffffffu, p0);
                if (w == w0)
                    mword &= ~((2ull << (r & 63)) - 1ull);   // clear j<=r (works for r&63==63)
                if (lane == 0) smask[r * W_MAX + w] = mword;
                nz |= mword;
            }
            if (lane == 0 && nz)
                atomicOr(&rownz[r >> 6], 1ull << (r & 63));
        }
        __syncthreads();

        // ---- sparse greedy chase, single thread, removed[] in registers ----
        if (tid == 0) {
            ull rem0 = 0, rem1 = 0, rem2 = 0, rem3 = 0;
            #pragma unroll
            for (int w = 0; w < W_MAX; w++) {
                if (w >= W) break;
                ull act = rownz[w];
                ull rw  = (w == 0) ? rem0 : (w == 1) ? rem1 : (w == 2) ? rem2 : rem3;
                act &= ~rw;
                while (act) {
                    const int bit = __ffsll((long long)act) - 1;
                    act &= act - 1;
                    if (!((rw >> bit) & 1ull)) {
                        const int i = (w << 6) + bit;
                        const ull* row = &smask[i * W_MAX];
                        if (w <= 0)          rem0 |= row[0];
                        if (w <= 1 && W > 1) rem1 |= row[1];
                        if (w <= 2 && W > 2) rem2 |= row[2];
                        if (w <= 3 && W > 3) rem3 |= row[3];
                        rw = (w == 0) ? rem0 : (w == 1) ? rem1 : (w == 2) ? rem2 : rem3;
                        act &= ~rw;
                    }
                }
            }
            keepw[0] = ~rem0; keepw[1] = ~rem1; keepw[2] = ~rem2; keepw[3] = ~rem3;
        }
        __syncthreads();

        // ---- output this bucket's rows (SMEM only) ----
        for (int m = tid; m < cnt; m += NMS_THR) {
            const bool kp = (keepw[m >> 6] >> (m & 63)) & 1ull;
            const float f = kp ? 1.0f : 0.0f;
            const float4 bb = bx[m];
            const size_t o = ((size_t)img * K_TOT + rk[m]) * 5;
            out[o + 0] = bb.x * f;
            out[o + 1] = bb.y * f;
            out[o + 2] = bb.z * f;
            out[o + 3] = bb.w * f;
            out[o + 4] = sc[m] * f;
        }
    } else {
        // ---- fallback (cnt > CAP): warp-serial kept-list from global ----
        __shared__ short kidx[K_TOT];
        if (warp == 0) {
            int nk = 0;
            for (int cix = 0; cix < cnt; cix++) {
                const float4 bc = g_bbx[gbase + cix];
                const float  ac = (bc.z - bc.x) * (bc.w - bc.y);
                bool sup = false;
                for (int k = lane; k < nk; k += 32) {
                    const float4 bk = g_bbx[gbase + kidx[k]];
                    const float  ak = (bk.z - bk.x) * (bk.w - bk.y);
                    if (iou_gt(bc, ac, bk, ak)) { sup = true; break; }
                }
                sup = (__ballot_sync(0xffffffffu, sup) != 0u);
                if (!sup) {
                    if (lane == 0) kidx[nk] = (short)cix;
                    nk++;
                }
                if (lane == 0) {
                    const float4 ax = g_aux[gbase + cix];
                    const float f = sup ? 0.0f : 1.0f;
                    const size_t o = ((size_t)img * K_TOT + (int)ax.z) * 5;
                    out[o + 0] = bc.x * f;
                    out[o + 1] = bc.y * f;
                    out[o + 2] = bc.z * f;
                    out[o + 3] = bc.w * f;
                    out[o + 4] = ax.x * f;
                }
                __syncwarp();
            }
        }
    }
}

// =============================================================================
extern "C" void kernel_launch(void* const* d_in, const int* in_sizes, int n_in,
                              void* d_out, int out_size) {
    const float* boxes   = (const float*)d_in[0];
    const float* scores  = (const float*)d_in[1];
    const int*   labels  = (const int*)  d_in[2];
    const float* weights = (const float*)d_in[3];
    float*       out     = (float*)d_out;

    k_sort<<<B_IMG, SORT_THR, PAD * 8 + K_TOT * 16>>>(boxes, scores, labels, weights);

    cudaLaunchConfig_t cfg = {};
    cfg.gridDim  = dim3(B_IMG * NUM_CLS);
    cfg.blockDim = dim3(NMS_THR);
    cfg.dynamicSmemBytes = 0;
    cfg.stream = 0;
    cudaLaunchAttribute attr[1];
    attr[0].id = cudaLaunchAttributeProgrammaticStreamSerialization;
    attr[0].val.programmaticStreamSerializationAllowed = 1;
    cfg.attrs = attr;
    cfg.numAttrs = 1;
    cudaLaunchKernelEx(&cfg, k_nms, out);
}

// round 14
// speedup vs baseline: 1.4374x; 1.3771x over previous
#include <cuda_runtime.h>
#include <cuda_bf16.h>
#include <cstdint>

typedef unsigned long long ull;

#define M_MODELS 3
#define B_IMG    16
#define N_BOX    512
#define K_TOT    (M_MODELS * N_BOX)   // 1536
#define PAD      2048
#define NUM_CLS  12
#define CAPX     512                  // bucket extraction capacity
#define CAP      256                  // matrix fast-path capacity
#define W_MAX    4                    // CAP/64
#define THR      512
#define GRID     (B_IMG + B_IMG * NUM_CLS)   // 16 + 192 = 208

// ---------------- device scratch ----------------
__device__ float4        g_sbox[B_IMG * K_TOT];   // boxes by global rank
__device__ ull           g_skey[B_IMG * K_TOT];   // sort keys by global rank
__device__ unsigned char g_keep[B_IMG * K_TOT];   // keep flag by ORIGINAL element
__device__ int           g_done[B_IMG];           // arrival counters (reset each run)

__device__ __forceinline__ void cswap(ull& x, ull& y, bool up) {
    if ((x > y) == up) { ull t = x; x = y; y = t; }
}

__device__ __forceinline__ ull shfl_stage(ull v, int e, unsigned j, unsigned ks) {
    const ull  o     = __shfl_xor_sync(0xffffffffu, v, j);
    const bool up    = ((e & ks) == 0);
    const bool lower = ((e & j) == 0);
    return ((v < o) == (lower == up)) ? v : o;
}

// division-free exact IoU>0.5 test: 0.5*d is exact in fp32
__device__ __forceinline__ bool iou_gt(const float4 bi, const float ai,
                                       const float4 bj, const float aj) {
    const float iw = fmaxf(fminf(bi.z, bj.z) - fmaxf(bi.x, bj.x), 0.0f);
    const float ih = fmaxf(fminf(bi.w, bj.w) - fmaxf(bi.y, bj.y), 0.0f);
    const float inter = iw * ih;
    const float uni   = ai + aj - inter;
    return inter > 0.5f * fmaxf(uni, 1e-9f);
}

struct NmsSh {
    ull    skey[CAPX];        // bucket keys (extraction order)
    ull    rkey[CAPX];        // bucket keys (rank order)
    float4 bx[CAPX];
    float  ar[CAPX];
    ull    smask[CAP * W_MAX];
    ull    rownz[W_MAX];
    ull    keepw[W_MAX];
};
union ShU {
    ull   key[PAD];           // sorter role (16 KB)
    NmsSh n;                  // nms role (~26.4 KB)
};

// =============================================================================
// ONE kernel, 208 blocks: 16 sorter blocks (global bitonic sort, independent)
// run CONCURRENTLY with 192 NMS blocks (per-class rank-count sort + matrix +
// chase, independent of global sort). Last of the 13 blocks per image joins
// rank data with keep flags and writes the output.
// =============================================================================
__global__ __launch_bounds__(THR)
void k_fused(const float* __restrict__ boxes, const float* __restrict__ scores,
             const int* __restrict__ labels, const float* __restrict__ weights,
             float* __restrict__ out) {
    __shared__ ShU sh;
    __shared__ int s_cnt, s_last;

    const int bid  = blockIdx.x;
    const int tid  = threadIdx.x;
    const int warp = tid >> 5, lane = tid & 31;

    const float w0 = weights[0], w1 = weights[1], w2 = weights[2];

    int img;

    if (bid < B_IMG) {
        // =================== SORTER ROLE ===================
        img = bid;
        ull* key = sh.key;
        const int W0 = warp << 7;   // 128-element window base

        auto mkkey = [&](int s) -> ull {
            if (s >= K_TOT) return ~0ull;
            const int m = s >> 9, n = s & (N_BOX - 1);
            const float wm = (m == 0) ? w0 : ((m == 1) ? w1 : w2);
            const float sc = scores[(m * B_IMG + img) * N_BOX + n] * wm;
            return ((ull)(~__float_as_uint(sc)) << 32) | (unsigned)s;
        };

        int e0 = W0 + lane, e1 = e0 + 32, e2 = e0 + 64, e3 = e0 + 96;
        ull v0 = mkkey(e0), v1 = mkkey(e1), v2 = mkkey(e2), v3 = mkkey(e3);

        // register phase: kstage 2..128 warp-local
        #pragma unroll
        for (int kb = 1; kb <= 5; kb++) {
            const unsigned ks = 1u << kb;
            const unsigned jstart = (ks > 32) ? 16u : (ks >> 1);
            #pragma unroll
            for (unsigned j = jstart; j >= 1; j >>= 1) {
                v0 = shfl_stage(v0, e0, j, ks);
                v1 = shfl_stage(v1, e1, j, ks);
                v2 = shfl_stage(v2, e2, j, ks);
                v3 = shfl_stage(v3, e3, j, ks);
            }
        }
        {   // ks = 64
            const unsigned ks = 64;
            cswap(v0, v1, ((e0 & ks) == 0));
            cswap(v2, v3, ((e2 & ks) == 0));
            #pragma unroll
            for (unsigned j = 16; j >= 1; j >>= 1) {
                v0 = shfl_stage(v0, e0, j, ks);
                v1 = shfl_stage(v1, e1, j, ks);
                v2 = shfl_stage(v2, e2, j, ks);
                v3 = shfl_stage(v3, e3, j, ks);
            }
        }
        {   // ks = 128
            const unsigned ks = 128;
            const bool up = ((e0 & ks) == 0);
            cswap(v0, v2, up); cswap(v1, v3, up);
            cswap(v0, v1, up); cswap(v2, v3, up);
            #pragma unroll
            for (unsigned j = 16; j >= 1; j >>= 1) {
                v0 = shfl_stage(v0, e0, j, ks);
                v1 = shfl_stage(v1, e1, j, ks);
                v2 = shfl_stage(v2, e2, j, ks);
                v3 = shfl_stage(v3, e3, j, ks);
            }
        }
        key[e0] = v0; key[e1] = v1; key[e2] = v2; key[e3] = v3;

        // smem phase: kstage 256..2048, j>=128 via smem
        #pragma unroll
        for (unsigned ks = 256; ks <= PAD; ks <<= 1) {
            for (unsigned j = ks >> 1; j >= 128; j >>= 1) {
                __syncthreads();
                #pragma unroll
                for (int t = tid; t < 1024; t += THR) {
                    const unsigned i = (((unsigned)t & ~(j - 1)) << 1) | ((unsigned)t & (j - 1));
                    const unsigned p = i | j;
                    const ull x = key[i];
                    const ull y = key[p];
                    const bool up = ((i & ks) == 0);
                    if ((x > y) == up) { key[i] = y; key[p] = x; }
                }
            }
            __syncthreads();
            v0 = key[e0]; v1 = key[e1]; v2 = key[e2]; v3 = key[e3];
            const bool up = ((e0 & ks) == 0);
            cswap(v0, v2, up); cswap(v1, v3, up);
            cswap(v0, v1, up); cswap(v2, v3, up);
            #pragma unroll
            for (unsigned j = 16; j >= 1; j >>= 1) {
                v0 = shfl_stage(v0, e0, j, ks);
                v1 = shfl_stage(v1, e1, j, ks);
                v2 = shfl_stage(v2, e2, j, ks);
                v3 = shfl_stage(v3, e3, j, ks);
            }
            key[e0] = v0; key[e1] = v1; key[e2] = v2; key[e3] = v3;
        }
        __syncthreads();

        // write (box, key) by rank
        for (int r = tid; r < K_TOT; r += THR) {
            const ull kk = key[r];
            const int e = (int)(kk & 0xffffffffu);
            const int m = e >> 9, n = e & (N_BOX - 1);
            g_sbox[(size_t)img * K_TOT + r] =
                *(const float4*)&boxes[(((size_t)m * B_IMG + img) * N_BOX + n) * 4];
            g_skey[(size_t)img * K_TOT + r] = kk;
        }
    } else {
        // =================== NMS ROLE ===================
        const int idx = bid - B_IMG;
        img = idx / NUM_CLS;
        const int cls = idx % NUM_CLS;

        if (tid == 0) s_cnt = 0;
        __syncthreads();

        // ---- extract class members (order irrelevant; sorted below) ----
        for (int e = tid; e < K_TOT; e += THR) {
            const int m = e >> 9, n = e & (N_BOX - 1);
            const bool p = (labels[(m * B_IMG + img) * N_BOX + n] == cls);
            ull kk = 0;
            if (p) {
                const float wm = (m == 0) ? w0 : ((m == 1) ? w1 : w2);
                const float sc = scores[(m * B_IMG + img) * N_BOX + n] * wm;
                kk = ((ull)(~__float_as_uint(sc)) << 32) | (unsigned)e;
            }
            const unsigned bal = __ballot_sync(0xffffffffu, p);
            int base = 0;
            if (lane == 0 && bal) base = atomicAdd(&s_cnt, __popc(bal));
            base = __shfl_sync(0xffffffffu, base, 0);
            if (p) sh.n.skey[base + __popc(bal & ((1u << lane) - 1u))] = kk;
        }
        __syncthreads();
        const int cnt = s_cnt;   // ~128, capacity CAPX=512

        // ---- rank-by-counting sort (keys distinct: idx in low bits) ----
        for (int m = tid; m < cnt; m += THR) {
            const ull k = sh.n.skey[m];
            int r = 0;
            for (int j = 0; j < cnt; j++) r += (sh.n.skey[j] < k);
            sh.n.rkey[r] = k;
        }
        if (tid < W_MAX) { sh.n.rownz[tid] = 0ull; sh.n.keepw[tid] = ~0ull; }
        __syncthreads();

        // ---- gather boxes in rank order (+ sentinels for matrix path) ----
        const int W    = (cnt + 63) >> 6;
        const int cpad = (cnt <= CAP) ? (W << 6) : cnt;
        for (int m = tid; m < cpad; m += THR) {
            if (m < cnt) {
                const int e = (int)(sh.n.rkey[m] & 0xffffffffu);
                const int mm = e >> 9, nn = e & (N_BOX - 1);
                const float4 bb =
                    *(const float4*)&boxes[(((size_t)mm * B_IMG + img) * N_BOX + nn) * 4];
                sh.n.bx[m] = bb;
                sh.n.ar[m] = (bb.z - bb.x) * (bb.w - bb.y);
            } else {
                sh.n.bx[m] = make_float4(3e8f, 3e8f, 3e8f, 3e8f);  // never suppresses
                sh.n.ar[m] = 0.0f;
            }
        }
        __syncthreads();

        if (cnt > 0 && cnt <= CAP) {
            // ---- branch-free matrix build: rows striped over 16 warps ----
            for (int r = warp; r < cnt; r += 16) {
                const float4 bi = sh.n.bx[r];
                const float  ai = sh.n.ar[r];
                const int    wlo = r >> 6;
                ull nz = 0ull;
                for (int w = wlo; w < W; w++) {
                    const int j0 = (w << 6) + lane;
                    const bool p0 = iou_gt(bi, ai, sh.n.bx[j0],      sh.n.ar[j0]);
                    const bool p1 = iou_gt(bi, ai, sh.n.bx[j0 + 32], sh.n.ar[j0 + 32]);
                    ull mword = ((ull)__ballot_sync(0xffffffffu, p1) << 32)
                              |        __ballot_sync(0xffffffffu, p0);
                    if (w == wlo)
                        mword &= ~((2ull << (r & 63)) - 1ull);   // clear j<=r
                    if (lane == 0) sh.n.smask[r * W_MAX + w] = mword;
                    nz |= mword;
                }
                if (lane == 0 && nz)
                    atomicOr(&sh.n.rownz[r >> 6], 1ull << (r & 63));
            }
            __syncthreads();

            // ---- sparse greedy chase, single thread, registers ----
            if (tid == 0) {
                ull rem0 = 0, rem1 = 0, rem2 = 0, rem3 = 0;
                #pragma unroll
                for (int w = 0; w < W_MAX; w++) {
                    if (w >= W) break;
                    ull act = sh.n.rownz[w];
                    ull rw  = (w == 0) ? rem0 : (w == 1) ? rem1 : (w == 2) ? rem2 : rem3;
                    act &= ~rw;
                    while (act) {
                        const int bit = __ffsll((long long)act) - 1;
                        act &= act - 1;
                        if (!((rw >> bit) & 1ull)) {
                            const int i = (w << 6) + bit;
                            const ull* row = &sh.n.smask[i * W_MAX];
                            if (w <= 0)          rem0 |= row[0];
                            if (w <= 1 && W > 1) rem1 |= row[1];
                            if (w <= 2 && W > 2) rem2 |= row[2];
                            if (w <= 3 && W > 3) rem3 |= row[3];
                            rw = (w == 0) ? rem0 : (w == 1) ? rem1 : (w == 2) ? rem2 : rem3;
                            act &= ~rw;
                        }
                    }
                }
                sh.n.keepw[0] = ~rem0; sh.n.keepw[1] = ~rem1;
                sh.n.keepw[2] = ~rem2; sh.n.keepw[3] = ~rem3;
            }
            __syncthreads();

            // ---- write keep flags by ORIGINAL element index ----
            for (int m = tid; m < cnt; m += THR) {
                const int e = (int)(sh.n.rkey[m] & 0xffffffffu);
                g_keep[(size_t)img * K_TOT + e] =
                    (unsigned char)((sh.n.keepw[m >> 6] >> (m & 63)) & 1ull);
            }
        } else if (cnt > CAP) {
            // ---- fallback: warp-serial kept-list over smem (rank order) ----
            short* klist = (short*)sh.n.smask;
            if (warp == 0) {
                int nk = 0;
                for (int c = 0; c < cnt; c++) {
                    const float4 bc = sh.n.bx[c];
                    const float  ac = sh.n.ar[c];
                    bool sup = false;
                    for (int k = lane; k < nk; k += 32) {
                        const int rr = klist[k];
                        if (iou_gt(bc, ac, sh.n.bx[rr], sh.n.ar[rr])) { sup = true; break; }
                    }
                    sup = (__ballot_sync(0xffffffffu, sup) != 0u);
                    if (!sup) {
                        if (lane == 0) klist[nk] = (short)c;
                        nk++;
                    }
                    if (lane == 0) {
                        const int e = (int)(sh.n.rkey[c] & 0xffffffffu);
                        g_keep[(size_t)img * K_TOT + e] = (unsigned char)(sup ? 0 : 1);
                    }
                    __syncwarp();
                }
            }
        }
    }

    // ================= arrival + epilogue by last block of the image =========
    __threadfence();          // make this block's global writes device-visible
    __syncthreads();          // ... before tid0 announces arrival
    if (tid == 0) {
        const int old = atomicAdd(&g_done[img], 1);
        s_last = (old == NUM_CLS);            // 13th arrival (0..12)
        if (s_last) __threadfence();          // acquire side
    }
    __syncthreads();

    if (s_last) {
        for (int r = tid; r < K_TOT; r += THR) {
            const ull kk = g_skey[(size_t)img * K_TOT + r];
            const int e = (int)(kk & 0xffffffffu);
            const float sc = __uint_as_float(~(unsigned)(kk >> 32));
            const float f = g_keep[(size_t)img * K_TOT + e] ? 1.0f : 0.0f;
            const float4 bb = g_sbox[(size_t)img * K_TOT + r];
            const size_t o = ((size_t)img * K_TOT + r) * 5;
            out[o + 0] = bb.x * f;
            out[o + 1] = bb.y * f;
            out[o + 2] = bb.z * f;
            out[o + 3] = bb.w * f;
            out[o + 4] = sc * f;
        }
        __syncthreads();
        if (tid == 0) g_done[img] = 0;   // reset for next graph replay
    }
}

// =============================================================================
extern "C" void kernel_launch(void* const* d_in, const int* in_sizes, int n_in,
                              void* d_out, int out_size) {
    const float* boxes   = (const float*)d_in[0];
    const float* scores  = (const float*)d_in[1];
    const int*   labels  = (const int*)  d_in[2];
    const float* weights = (const float*)d_in[3];
    float*       out     = (float*)d_out;

    k_fused<<<GRID, THR>>>(boxes, scores, labels, weights, out);
}